// round 3
// baseline (speedup 1.0000x reference)
#include <cuda_runtime.h>

#define N_NODES 20000
#define IN_DIM 256
#define HID 128
#define OUT_DIM 64
#define N_LAYERS 4
#define N_PATHS 8
#define PATH_LEN 8
#define N_TYPES 2

// -------- scratch (no allocations allowed; device globals) --------
__device__ float g_in_feats[N_NODES * HID];
__device__ float g_bufA[N_NODES * HID];
__device__ float g_bufB[N_NODES * HID];
__device__ float g_fout[N_NODES * N_TYPES * HID];

__device__ __forceinline__ float* buf_ptr(int s) {
    return s == 0 ? g_in_feats : (s == 1 ? g_bufA : g_bufB);
}

// ============================================================================
// Tiled SGEMM:  C[M, BN] = EPI( A[M, KDIM] @ W[BN, KDIM]^T )
//   EPI==0: relu(acc + bias[n])
//   EPI==1: 0.8*relu(acc) + 0.1*pre + 0.1*inf
// Block tile: 64 x BN, 256 threads, per-thread 4 x TN microtile.
// Grid = 313 blocks -> no wave quantization (vs 157 @ BM=128).
// ============================================================================
template <int KDIM, int BN, int TN, int EPI>
__device__ __forceinline__ void gemm_body(
    const float* __restrict__ A, const float* __restrict__ W,
    const float* __restrict__ bias, const float* __restrict__ pre,
    const float* __restrict__ inf, float* __restrict__ C)
{
    constexpr int BM = 64, BK = 16, TM = 4;
    __shared__ float As[BK][BM];
    __shared__ float Bs[BK][BN];

    const int tid  = threadIdx.x;
    const int tcol = tid % (BN / TN);   // 16 thread-cols
    const int trow = tid / (BN / TN);   // 16 thread-rows
    const int m0   = blockIdx.x * BM;

    float acc[TM][TN];
#pragma unroll
    for (int i = 0; i < TM; i++)
#pragma unroll
        for (int j = 0; j < TN; j++) acc[i][j] = 0.f;

    // A-tile loader: each thread loads 4 consecutive k of one row
    const int  am      = tid >> 2;        // 0..63
    const int  ak      = (tid & 3) << 2;  // 0,4,8,12
    const bool arow_ok = (m0 + am) < N_NODES;
    const float* Arow  = A + (size_t)(m0 + am) * KDIM + ak;

    for (int k0 = 0; k0 < KDIM; k0 += BK) {
        // ---- A tile (64x16) -> As[k][m] ----
        float4 va = make_float4(0.f, 0.f, 0.f, 0.f);
        if (arow_ok) va = *(const float4*)(Arow + k0);
        As[ak + 0][am] = va.x; As[ak + 1][am] = va.y;
        As[ak + 2][am] = va.z; As[ak + 3][am] = va.w;

        // ---- W tile (BN x 16) -> Bs[k][n] ----
        if constexpr (BN == 128) {
            int bn = tid >> 1, bk = (tid & 1) << 3;
            float4 v0 = *(const float4*)(W + (size_t)bn * KDIM + k0 + bk);
            float4 v1 = *(const float4*)(W + (size_t)bn * KDIM + k0 + bk + 4);
            Bs[bk + 0][bn] = v0.x; Bs[bk + 1][bn] = v0.y;
            Bs[bk + 2][bn] = v0.z; Bs[bk + 3][bn] = v0.w;
            Bs[bk + 4][bn] = v1.x; Bs[bk + 5][bn] = v1.y;
            Bs[bk + 6][bn] = v1.z; Bs[bk + 7][bn] = v1.w;
        } else {  // BN == 64
            int bn = tid >> 2, bk = (tid & 3) << 2;
            float4 v0 = *(const float4*)(W + (size_t)bn * KDIM + k0 + bk);
            Bs[bk + 0][bn] = v0.x; Bs[bk + 1][bn] = v0.y;
            Bs[bk + 2][bn] = v0.z; Bs[bk + 3][bn] = v0.w;
        }
        __syncthreads();

#pragma unroll
        for (int k = 0; k < BK; k++) {
            float a[TM], b[TN];
            *(float4*)&a[0] = *(const float4*)&As[k][trow * TM];
            *(float4*)&b[0] = *(const float4*)&Bs[k][tcol * TN];
            if constexpr (TN == 8)
                *(float4*)&b[4] = *(const float4*)&Bs[k][tcol * TN + 4];
#pragma unroll
            for (int i = 0; i < TM; i++)
#pragma unroll
                for (int j = 0; j < TN; j++)
                    acc[i][j] = fmaf(a[i], b[j], acc[i][j]);
        }
        __syncthreads();
    }

    // ---- epilogue (float4 stores) ----
#pragma unroll
    for (int i = 0; i < TM; i++) {
        int m = m0 + trow * TM + i;
        if (m >= N_NODES) continue;
        size_t rowoff = (size_t)m * BN + tcol * TN;
#pragma unroll
        for (int j = 0; j < TN; j += 4) {
            float4 v;
            v.x = acc[i][j + 0]; v.y = acc[i][j + 1];
            v.z = acc[i][j + 2]; v.w = acc[i][j + 3];
            if constexpr (EPI == 0) {
                int n = tcol * TN + j;
                v.x += bias[n + 0]; v.y += bias[n + 1];
                v.z += bias[n + 2]; v.w += bias[n + 3];
                v.x = fmaxf(v.x, 0.f); v.y = fmaxf(v.y, 0.f);
                v.z = fmaxf(v.z, 0.f); v.w = fmaxf(v.w, 0.f);
            } else {
                float4 p4 = *(const float4*)(pre + rowoff + j);
                float4 f4 = *(const float4*)(inf + rowoff + j);
                v.x = 0.8f * fmaxf(v.x, 0.f) + 0.1f * p4.x + 0.1f * f4.x;
                v.y = 0.8f * fmaxf(v.y, 0.f) + 0.1f * p4.y + 0.1f * f4.y;
                v.z = 0.8f * fmaxf(v.z, 0.f) + 0.1f * p4.z + 0.1f * f4.z;
                v.w = 0.8f * fmaxf(v.w, 0.f) + 0.1f * p4.w + 0.1f * f4.w;
            }
            *(float4*)(C + rowoff + j) = v;
        }
    }
}

__global__ void __launch_bounds__(256, 4)
fc_in_kernel(const float* __restrict__ x, const float* __restrict__ w,
             const float* __restrict__ b)
{
    gemm_body<IN_DIM, HID, 8, 0>(x, w, b, nullptr, nullptr, g_in_feats);
}

__global__ void __launch_bounds__(256, 4)
layer_gemm_kernel(const float* __restrict__ w, int pre_sel, int out_sel)
{
    gemm_body<N_TYPES * HID, HID, 8, 1>(g_fout, w, nullptr,
                                        buf_ptr(pre_sel), g_in_feats,
                                        buf_ptr(out_sel));
}

__global__ void __launch_bounds__(256, 4)
fc_out_kernel(const float* __restrict__ w, const float* __restrict__ b,
              float* __restrict__ out, int feats_sel)
{
    gemm_body<HID, OUT_DIM, 4, 0>(buf_ptr(feats_sel), w, b, nullptr, nullptr, out);
}

// ============================================================================
// Gather + per-type mean (float2, weights in SHARED to keep regs low):
//   fout[n, t*128 + h] = mean_{p: type(p)==t} sum_l feats[paths[p,n,l], h] * pw[t,l,h]
// 4 nodes per 256-thread block; 64 threads per node, 2 lanes per thread.
// ============================================================================
__global__ void __launch_bounds__(256)
gather_kernel(const int* __restrict__ paths, const int* __restrict__ ptypes,
              const float* __restrict__ pw, int feats_sel)
{
    const float2* __restrict__ feats2 = (const float2*)buf_ptr(feats_sel);
    const float2* __restrict__ pw2    = (const float2*)pw;

    // type-resolved per-path weights: wp_s[p][l][lane]
    __shared__ float2 wp_s[N_PATHS][PATH_LEN][HID / 2];   // 32 KB
    __shared__ int    idx_s[4][N_PATHS * PATH_LEN];
    __shared__ int    types_s[N_PATHS];

    const int tid  = threadIdx.x;
    const int slot = tid >> 6;       // 0..3
    const int hh   = tid & 63;       // float2 lane
    const int n    = blockIdx.x * 4 + slot;

    if (tid < N_PATHS) types_s[tid] = ptypes[tid];
    {
        int p = hh >> 3, l = hh & 7;
        idx_s[slot][hh] = paths[p * (N_NODES * PATH_LEN) + n * PATH_LEN + l];
    }
    // fill resolved weights: 8*8*64 = 4096 float2, 16 per thread
#pragma unroll
    for (int i = tid; i < N_PATHS * PATH_LEN * (HID / 2); i += 256) {
        int p = i >> 9;             // /512
        int l = (i >> 6) & 7;
        int lane = i & 63;
        int t = __ldg(ptypes + p);
        wp_s[p][l][lane] = pw2[(t * PATH_LEN + l) * (HID / 2) + lane];
    }
    __syncthreads();

    float2 acc0 = make_float2(0.f, 0.f), acc1 = make_float2(0.f, 0.f);
    int c0 = 0, c1 = 0;
#pragma unroll
    for (int p = 0; p < N_PATHS; p++) {
        float2 a = make_float2(0.f, 0.f);
        float2 b = make_float2(0.f, 0.f);
#pragma unroll
        for (int l = 0; l < PATH_LEN; l += 2) {
            float2 f0 = __ldg(feats2 +
                (size_t)idx_s[slot][p * PATH_LEN + l] * (HID / 2) + hh);
            float2 f1 = __ldg(feats2 +
                (size_t)idx_s[slot][p * PATH_LEN + l + 1] * (HID / 2) + hh);
            float2 w0 = wp_s[p][l][hh];
            float2 w1 = wp_s[p][l + 1][hh];
            a.x = fmaf(f0.x, w0.x, a.x);
            a.y = fmaf(f0.y, w0.y, a.y);
            b.x = fmaf(f1.x, w1.x, b.x);
            b.y = fmaf(f1.y, w1.y, b.y);
        }
        a.x += b.x; a.y += b.y;
        if (types_s[p]) { acc1.x += a.x; acc1.y += a.y; c1++; }
        else            { acc0.x += a.x; acc0.y += a.y; c0++; }
    }

    float inv0 = 1.0f / (float)c0, inv1 = 1.0f / (float)c1;
    float2* fo2 = (float2*)(g_fout + (size_t)n * (N_TYPES * HID));
    fo2[hh]           = make_float2(acc0.x * inv0, acc0.y * inv0);
    fo2[HID / 2 + hh] = make_float2(acc1.x * inv1, acc1.y * inv1);
}

// ============================================================================
extern "C" void kernel_launch(void* const* d_in, const int* in_sizes, int n_in,
                              void* d_out, int out_size)
{
    const float* input_x    = (const float*)d_in[0];
    const int*   paths      = (const int*)d_in[1];
    const int*   ptypes     = (const int*)d_in[2];
    const float* fc_in_w    = (const float*)d_in[3];
    const float* fc_in_b    = (const float*)d_in[4];
    const float* fc_out_w   = (const float*)d_in[5];
    const float* fc_out_b   = (const float*)d_in[6];
    const float* layer_fc_w = (const float*)d_in[7];
    const float* path_w     = (const float*)d_in[8];
    float* out = (float*)d_out;

    const dim3 blk(256);
    const dim3 ggrd((N_NODES + 63) / 64);

    fc_in_kernel<<<ggrd, blk>>>(input_x, fc_in_w, fc_in_b);

    int cur = 0;  // feats = g_in_feats
    for (int i = 0; i < N_LAYERS; i++) {
        gather_kernel<<<N_NODES / 4, blk>>>(
            paths, ptypes, path_w + (size_t)i * N_TYPES * PATH_LEN * HID, cur);
        int nxt = (cur == 1) ? 2 : 1;
        layer_gemm_kernel<<<ggrd, blk>>>(
            layer_fc_w + (size_t)i * HID * (N_TYPES * HID), cur, nxt);
        cur = nxt;
    }

    fc_out_kernel<<<ggrd, blk>>>(fc_out_w, fc_out_b, out, cur);
}

// round 4
// speedup vs baseline: 1.7188x; 1.7188x over previous
#include <cuda_runtime.h>
#include <cstdint>

#define N_NODES 20000
#define IN_DIM 256
#define HID 128
#define OUT_DIM 64
#define N_LAYERS 4
#define N_PATHS 8
#define PATH_LEN 8
#define N_TYPES 2

// -------- scratch (no allocations allowed; device globals) --------
__device__ float g_in_feats[N_NODES * HID];
__device__ float g_bufA[N_NODES * HID];
__device__ float g_bufB[N_NODES * HID];
__device__ float g_fout[N_NODES * N_TYPES * HID];

__device__ __forceinline__ float* buf_ptr(int s) {
    return s == 0 ? g_in_feats : (s == 1 ? g_bufA : g_bufB);
}

__device__ __forceinline__ uint32_t f2tf32(float f) {
    uint32_t u;
    asm("cvt.rna.tf32.f32 %0, %1;" : "=r"(u) : "f"(f));
    return u;
}

__device__ __forceinline__ void mma_tf32(
    float& d0, float& d1, float& d2, float& d3,
    uint32_t a0, uint32_t a1, uint32_t a2, uint32_t a3,
    uint32_t b0, uint32_t b1)
{
    asm volatile(
        "mma.sync.aligned.m16n8k8.row.col.f32.tf32.tf32.f32 "
        "{%0,%1,%2,%3}, {%4,%5,%6,%7}, {%8,%9}, {%0,%1,%2,%3};\n"
        : "+f"(d0), "+f"(d1), "+f"(d2), "+f"(d3)
        : "r"(a0), "r"(a1), "r"(a2), "r"(a3), "r"(b0), "r"(b1));
}

// ============================================================================
// TF32 tensor-core GEMM:  C[M, BN] = EPI( A[M, KDIM] @ W[BN, KDIM]^T )
//   EPI==0: relu(acc + bias[n])
//   EPI==1: 0.8*relu(acc) + 0.1*pre + 0.1*inf
// Block: 128 x BN tile, 256 threads (8 warps: 4 along M, 2 along N).
// Warp tile: 32 x (BN/2). mma.m16n8k8, BK=32 per smem stage.
// Smem stride padded to 36 -> conflict-free fragment loads.
// ============================================================================
template <int KDIM, int BN, int EPI>
__device__ __forceinline__ void gemm_tc_body(
    const float* __restrict__ A, const float* __restrict__ W,
    const float* __restrict__ bias, const float* __restrict__ pre,
    const float* __restrict__ inf, float* __restrict__ C)
{
    constexpr int BM = 128, BK = 32, LDS_ = 36;
    constexpr int NT = BN / 16;          // n8-tiles per warp (8 for BN=128, 4 for 64)
    __shared__ uint32_t As[BM * LDS_];
    __shared__ uint32_t Bs[BN * LDS_];

    const int tid    = threadIdx.x;
    const int lane   = tid & 31;
    const int warp   = tid >> 5;
    const int warp_m = warp & 3;          // 0..3  -> 32 rows each
    const int warp_n = warp >> 2;         // 0..1  -> NT*8 cols each
    const int gid    = lane >> 2;         // 0..7
    const int tig    = lane & 3;          // 0..3
    const int m0     = blockIdx.x * BM;

    float acc[2][NT][4];
#pragma unroll
    for (int mt = 0; mt < 2; mt++)
#pragma unroll
        for (int nt = 0; nt < NT; nt++)
#pragma unroll
            for (int r = 0; r < 4; r++) acc[mt][nt][r] = 0.f;

    // A loader: row = tid>>1 (0..127), 16 consecutive k starting at (tid&1)*16
    const int  a_row   = tid >> 1;
    const int  a_cb    = (tid & 1) << 4;
    const bool a_ok    = (m0 + a_row) < N_NODES;
    const float* Aptr  = A + (size_t)(m0 + a_row) * KDIM + a_cb;

    for (int k0 = 0; k0 < KDIM; k0 += BK) {
        // ---- stage A (128x32) ----
        {
            uint32_t* dst = As + a_row * LDS_ + a_cb;
#pragma unroll
            for (int i = 0; i < 4; i++) {
                float4 v = make_float4(0.f, 0.f, 0.f, 0.f);
                if (a_ok) v = *(const float4*)(Aptr + k0 + i * 4);
                uint4 u;
                u.x = f2tf32(v.x); u.y = f2tf32(v.y);
                u.z = f2tf32(v.z); u.w = f2tf32(v.w);
                *(uint4*)(dst + i * 4) = u;
            }
        }
        // ---- stage B (BN x 32) from W[BN, KDIM] ----
        if constexpr (BN == 128) {
            int row = tid >> 1, cb = (tid & 1) << 4;
            const float* Wp = W + (size_t)row * KDIM + k0 + cb;
            uint32_t* dst = Bs + row * LDS_ + cb;
#pragma unroll
            for (int i = 0; i < 4; i++) {
                float4 v = *(const float4*)(Wp + i * 4);
                uint4 u;
                u.x = f2tf32(v.x); u.y = f2tf32(v.y);
                u.z = f2tf32(v.z); u.w = f2tf32(v.w);
                *(uint4*)(dst + i * 4) = u;
            }
        } else {  // BN == 64
            int row = tid >> 2, cb = (tid & 3) << 3;
            const float* Wp = W + (size_t)row * KDIM + k0 + cb;
            uint32_t* dst = Bs + row * LDS_ + cb;
#pragma unroll
            for (int i = 0; i < 2; i++) {
                float4 v = *(const float4*)(Wp + i * 4);
                uint4 u;
                u.x = f2tf32(v.x); u.y = f2tf32(v.y);
                u.z = f2tf32(v.z); u.w = f2tf32(v.w);
                *(uint4*)(dst + i * 4) = u;
            }
        }
        __syncthreads();

#pragma unroll
        for (int kk = 0; kk < BK / 8; kk++) {
            const int kb = kk * 8;
            uint32_t a[2][4];
#pragma unroll
            for (int mt = 0; mt < 2; mt++) {
                int r = warp_m * 32 + mt * 16 + gid;
                a[mt][0] = As[r * LDS_ + kb + tig];
                a[mt][1] = As[(r + 8) * LDS_ + kb + tig];
                a[mt][2] = As[r * LDS_ + kb + tig + 4];
                a[mt][3] = As[(r + 8) * LDS_ + kb + tig + 4];
            }
            uint32_t b[NT][2];
#pragma unroll
            for (int nt = 0; nt < NT; nt++) {
                int c = warp_n * (NT * 8) + nt * 8 + gid;
                b[nt][0] = Bs[c * LDS_ + kb + tig];
                b[nt][1] = Bs[c * LDS_ + kb + tig + 4];
            }
#pragma unroll
            for (int mt = 0; mt < 2; mt++)
#pragma unroll
                for (int nt = 0; nt < NT; nt++)
                    mma_tf32(acc[mt][nt][0], acc[mt][nt][1],
                             acc[mt][nt][2], acc[mt][nt][3],
                             a[mt][0], a[mt][1], a[mt][2], a[mt][3],
                             b[nt][0], b[nt][1]);
        }
        __syncthreads();
    }

    // ---- epilogue: c0,c1 -> (row, col..col+1); c2,c3 -> (row+8, ...) ----
#pragma unroll
    for (int mt = 0; mt < 2; mt++) {
#pragma unroll
        for (int half = 0; half < 2; half++) {
            int row = m0 + warp_m * 32 + mt * 16 + half * 8 + gid;
            if (row >= N_NODES) continue;
#pragma unroll
            for (int nt = 0; nt < NT; nt++) {
                int col = warp_n * (NT * 8) + nt * 8 + 2 * tig;
                float v0 = acc[mt][nt][half * 2 + 0];
                float v1 = acc[mt][nt][half * 2 + 1];
                size_t off = (size_t)row * BN + col;
                if constexpr (EPI == 0) {
                    v0 = fmaxf(v0 + bias[col], 0.f);
                    v1 = fmaxf(v1 + bias[col + 1], 0.f);
                } else {
                    float2 p2 = *(const float2*)(pre + off);
                    float2 f2 = *(const float2*)(inf + off);
                    v0 = 0.8f * fmaxf(v0, 0.f) + 0.1f * p2.x + 0.1f * f2.x;
                    v1 = 0.8f * fmaxf(v1, 0.f) + 0.1f * p2.y + 0.1f * f2.y;
                }
                *(float2*)(C + off) = make_float2(v0, v1);
            }
        }
    }
}

__global__ void __launch_bounds__(256)
fc_in_kernel(const float* __restrict__ x, const float* __restrict__ w,
             const float* __restrict__ b)
{
    gemm_tc_body<IN_DIM, HID, 0>(x, w, b, nullptr, nullptr, g_in_feats);
}

__global__ void __launch_bounds__(256)
layer_gemm_kernel(const float* __restrict__ w, int pre_sel, int out_sel)
{
    gemm_tc_body<N_TYPES * HID, HID, 1>(g_fout, w, nullptr,
                                        buf_ptr(pre_sel), g_in_feats,
                                        buf_ptr(out_sel));
}

__global__ void __launch_bounds__(256)
fc_out_kernel(const float* __restrict__ w, const float* __restrict__ b,
              float* __restrict__ out, int feats_sel)
{
    gemm_tc_body<HID, OUT_DIM, 0>(buf_ptr(feats_sel), w, b, nullptr, nullptr, out);
}

// ============================================================================
// Gather + per-type mean (float4; l-outer loop keeps weight regs at 8):
//   fout[n, t*128+h] = mean_{p: type(p)==t} sum_l feats[paths[p,n,l], h]*pw[t,l,h]
// 1 warp per node (32 threads x float4 = 512B row), 8 nodes per 256-thr block.
// ============================================================================
__global__ void __launch_bounds__(256)
gather_kernel(const int* __restrict__ paths, const int* __restrict__ ptypes,
              const float* __restrict__ pw, int feats_sel)
{
    const float4* __restrict__ feats4 = (const float4*)buf_ptr(feats_sel);
    const float4* __restrict__ pw4    = (const float4*)pw;

    __shared__ int idx_s[8][N_PATHS * PATH_LEN];
    __shared__ int types_s[N_PATHS];

    const int tid  = threadIdx.x;
    const int slot = tid >> 5;       // node slot 0..7
    const int lane = tid & 31;       // float4 lane
    const int n    = blockIdx.x * 8 + slot;

    if (tid < N_PATHS) types_s[tid] = ptypes[tid];
    // 512 indices per block, 2 per thread (int2: consecutive l of one p)
    {
        int i  = tid * 2;
        int sl = i >> 6;                     // which node slot
        int r  = i & 63;
        int p  = r >> 3, l = r & 7;
        int nn = blockIdx.x * 8 + sl;
        int2 v = *(const int2*)(paths + (size_t)p * (N_NODES * PATH_LEN)
                                + (size_t)nn * PATH_LEN + l);
        idx_s[sl][r]     = v.x;
        idx_s[sl][r + 1] = v.y;
    }
    __syncthreads();

    unsigned tmask = 0;
#pragma unroll
    for (int p = 0; p < N_PATHS; p++)
        tmask |= (types_s[p] ? 1u : 0u) << p;
    const int c1 = __popc(tmask);
    const int c0 = N_PATHS - c1;

    float4 acc0 = make_float4(0.f, 0.f, 0.f, 0.f);
    float4 acc1 = make_float4(0.f, 0.f, 0.f, 0.f);

#pragma unroll
    for (int l = 0; l < PATH_LEN; l++) {
        const float4 w0 = pw4[(size_t)l * (HID / 4) + lane];
        const float4 w1 = pw4[(size_t)(PATH_LEN + l) * (HID / 4) + lane];
#pragma unroll
        for (int p = 0; p < N_PATHS; p++) {
            const float4 f = __ldg(feats4 +
                (size_t)idx_s[slot][p * PATH_LEN + l] * (HID / 4) + lane);
            const bool t1 = (tmask >> p) & 1;
            const float4 w = t1 ? w1 : w0;
            float4& a = t1 ? acc1 : acc0;
            a.x = fmaf(f.x, w.x, a.x);
            a.y = fmaf(f.y, w.y, a.y);
            a.z = fmaf(f.z, w.z, a.z);
            a.w = fmaf(f.w, w.w, a.w);
        }
    }

    const float inv0 = 1.0f / (float)c0, inv1 = 1.0f / (float)c1;
    float4* fo4 = (float4*)(g_fout + (size_t)n * (N_TYPES * HID));
    fo4[lane] = make_float4(acc0.x * inv0, acc0.y * inv0,
                            acc0.z * inv0, acc0.w * inv0);
    fo4[HID / 4 + lane] = make_float4(acc1.x * inv1, acc1.y * inv1,
                                      acc1.z * inv1, acc1.w * inv1);
}

// ============================================================================
extern "C" void kernel_launch(void* const* d_in, const int* in_sizes, int n_in,
                              void* d_out, int out_size)
{
    const float* input_x    = (const float*)d_in[0];
    const int*   paths      = (const int*)d_in[1];
    const int*   ptypes     = (const int*)d_in[2];
    const float* fc_in_w    = (const float*)d_in[3];
    const float* fc_in_b    = (const float*)d_in[4];
    const float* fc_out_w   = (const float*)d_in[5];
    const float* fc_out_b   = (const float*)d_in[6];
    const float* layer_fc_w = (const float*)d_in[7];
    const float* path_w     = (const float*)d_in[8];
    float* out = (float*)d_out;

    const dim3 blk(256);
    const dim3 ggrd((N_NODES + 127) / 128);

    fc_in_kernel<<<ggrd, blk>>>(input_x, fc_in_w, fc_in_b);

    int cur = 0;  // feats = g_in_feats
    for (int i = 0; i < N_LAYERS; i++) {
        gather_kernel<<<N_NODES / 8, blk>>>(
            paths, ptypes, path_w + (size_t)i * N_TYPES * PATH_LEN * HID, cur);
        int nxt = (cur == 1) ? 2 : 1;
        layer_gemm_kernel<<<ggrd, blk>>>(
            layer_fc_w + (size_t)i * HID * (N_TYPES * HID), cur, nxt);
        cur = nxt;
    }

    fc_out_kernel<<<ggrd, blk>>>(fc_out_w, fc_out_b, out, cur);
}